// round 2
// baseline (speedup 1.0000x reference)
#include <cuda_runtime.h>
#include <cuda_bf16.h>

// AdaptiveEMA: out[c,t] = windowed-EMA(x[c,:], alpha_c) / total_weight(t)
//   alpha = 0.5^(1/exp(log_halflife[f])), window K = 201 taps
// Strategy: infinite EMA e[t] via block-parallel linear-recurrence scan,
// then num[t] = e[t] - alpha^K * e[t-K]  (exact telescoping of the window),
// denom closed-form geometric series.
// One CTA per (b,f) channel: 256 threads x 16 elements = 4096 = S.

#define S_LEN 4096
#define TPB 256
#define PER_THREAD 16
#define KWIN 201
#define NWARPS (TPB / 32)

// padded smem index: stride-17 layout -> conflict-free scatter writes
__device__ __forceinline__ int pidx(int t) { return t + (t >> 4); }

__global__ __launch_bounds__(TPB) void adaptive_ema_kernel(
    const float* __restrict__ x,
    const float* __restrict__ log_hl,
    float* __restrict__ out,
    int F)
{
    __shared__ float e_s[S_LEN + (S_LEN / 16)];   // 4096 + 256 floats
    __shared__ float aggC[NWARPS], aggV[NWARPS];

    const int c    = blockIdx.x;          // channel = b*F + f
    const int f    = c % F;
    const int tid  = threadIdx.x;
    const int lane = tid & 31;
    const int wid  = tid >> 5;

    // ---- per-channel constants ----
    const float hl      = expf(log_hl[f]);
    const float inv_hl  = 1.0f / hl;
    const float a       = exp2f(-inv_hl);                          // alpha
    const float one_m_a = -expm1f(-0.69314718055994531f * inv_hl); // 1 - alpha, no cancellation
    const float inv_1ma = 1.0f / one_m_a;
    const float aK      = exp2f(-(float)KWIN * inv_hl);            // alpha^201
    const float tw_c    = (1.0f - aK) * inv_1ma;                   // steady-state weight sum
    const float r_const = 1.0f / (tw_c + 1e-8f);

    const float* xc = x   + (size_t)c * S_LEN;
    float*       oc = out + (size_t)c * S_LEN;

    // ---- load: thread owns contiguous 16 elements [16*tid, 16*tid+16) ----
    float v[PER_THREAD];
    const float4* xb = reinterpret_cast<const float4*>(xc + tid * PER_THREAD);
    #pragma unroll
    for (int q = 0; q < 4; q++) {
        float4 t4 = xb[q];
        v[4*q+0] = t4.x; v[4*q+1] = t4.y; v[4*q+2] = t4.z; v[4*q+3] = t4.w;
    }

    // ---- local serial scan: e = a*e + x ----
    float e = 0.0f;
    #pragma unroll
    for (int j = 0; j < PER_THREAD; j++) {
        e = fmaf(a, e, v[j]);
        v[j] = e;                         // v[] now holds local inclusive scan
    }

    // segment transform for this thread: E_out = C*E_in + V, C = a^16
    const float a2 = a * a, a4 = a2 * a2, a8 = a4 * a4;
    float C = a8 * a8;
    float V = e;

    // ---- Kogge-Stone warp scan of affine transforms ----
    #pragma unroll
    for (int d = 1; d < 32; d <<= 1) {
        float Cp = __shfl_up_sync(0xffffffffu, C, d);
        float Vp = __shfl_up_sync(0xffffffffu, V, d);
        if (lane >= d) {
            V = fmaf(C, Vp, V);
            C = C * Cp;
        }
    }
    if (lane == 31) { aggC[wid] = C; aggV[wid] = V; }

    // lane-exclusive transform (shift by one; lane 0 = identity)
    float Cx = __shfl_up_sync(0xffffffffu, C, 1);
    float Vx = __shfl_up_sync(0xffffffffu, V, 1);
    if (lane == 0) { Cx = 1.0f; Vx = 0.0f; }

    __syncthreads();

    // compose aggregates of all preceding warps (serial over <=7, cheap)
    float Wv = 0.0f;
    #pragma unroll
    for (int w = 0; w < NWARPS; w++) {
        if (w < wid) Wv = fmaf(aggC[w], Wv, aggV[w]);
    }
    // e just before this thread's segment:
    const float Ein = fmaf(Cx, Wv, Vx);

    // ---- apply carry, stage e into padded smem (stride-17 -> conflict-free) ----
    {
        float p = a;                      // a^(j+1)
        const int base = tid * PER_THREAD;
        #pragma unroll
        for (int j = 0; j < PER_THREAD; j++) {
            e_s[pidx(base + j)] = fmaf(p, Ein, v[j]);
            p *= a;
        }
    }
    __syncthreads();

    // ---- output phase: coalesced mapping t = tid + 256*k ----
    #pragma unroll
    for (int k = 0; k < PER_THREAD; k++) {
        const int t = tid + TPB * k;
        float num = e_s[pidx(t)];
        if (t >= KWIN) num = fmaf(-aK, e_s[pidx(t - KWIN)], num);
        float r;
        if (t < KWIN - 1) {
            // warm-up region: tw = (1 - a^(t+1)) / (1 - a)
            float tw = (1.0f - exp2f(-(float)(t + 1) * inv_hl)) * inv_1ma;
            r = __fdividef(1.0f, tw + 1e-8f);
        } else {
            r = r_const;
        }
        oc[t] = num * r;
    }
}

extern "C" void kernel_launch(void* const* d_in, const int* in_sizes, int n_in,
                              void* d_out, int out_size)
{
    const float* x      = (const float*)d_in[0];
    const float* log_hl = (const float*)d_in[1];
    float*       out    = (float*)d_out;

    const int F        = in_sizes[1];             // 256
    const int channels = in_sizes[0] / S_LEN;     // B*F = 8192

    adaptive_ema_kernel<<<channels, TPB>>>(x, log_hl, out, F);
}